// round 1
// baseline (speedup 1.0000x reference)
#include <cuda_runtime.h>
#include <math.h>

#define FULLMASK 0xffffffffu

#define BB 2
#define KK 2048
#define NN 16384
#define SROWS 65536      // B*K*16 sample-rows
#define ROWS 4096        // B*K
#define CBEV 256
#define HBEV 100
#define WBEV 176
#define FEAT_DIM 304
#define OUTC 128

// ---------------- scratch (device globals; no allocs allowed) ----------------
__device__ float4 g_g0[SROWS];            // grouped scale0: (rel xyz, feat)
__device__ float4 g_g1[SROWS];            // grouped scale1
__device__ unsigned char g_e0[ROWS];
__device__ unsigned char g_e1[ROWS];
__device__ float4 g_z0[SROWS * 4];        // layer0 pre-BN output (16 ch)
__device__ float4 g_z1[SROWS * 8];        // layer1 pre-BN output (<=32 ch)
__device__ float g_feats[ROWS * FEAT_DIM];
__device__ float g_fz[ROWS * OUTC];
__device__ float g_acc[512];              // stat accumulators

// acc layout: [0:32) s0 l0 (sum16,sq16); [32:64) s0 l1; [64:96) s1 l0;
//             [96:160) s1 l1 (sum32,sq32); [160:416) final (sum128,sq128)

__global__ void k_zero() {
    if (threadIdx.x < 512) g_acc[threadIdx.x] = 0.f;
}

// ---------------- BEV bilinear gather -> feats[:, 0:256] --------------------
__global__ void k_bev(const float* __restrict__ kp, const float* __restrict__ sf,
                      const int* __restrict__ pstride) {
    int row = blockIdx.x;                  // 0..4095
    int b = row >> 11;
    float stride = (float)pstride[0];
    float kx = kp[row * 3 + 0];
    float ky = kp[row * 3 + 1];
    float x = (kx - (-70.4f)) / 0.1f / stride;
    float y = (ky - (-40.0f)) / 0.1f / stride;
    int xi = (int)floorf(x), yi = (int)floorf(y);
    int x0 = min(max(xi, 0), WBEV - 1), x1 = min(max(xi + 1, 0), WBEV - 1);
    int y0 = min(max(yi, 0), HBEV - 1), y1 = min(max(yi + 1, 0), HBEV - 1);
    float x0f = (float)x0, x1f = (float)x1, y0f = (float)y0, y1f = (float)y1;
    float wa = (x1f - x) * (y1f - y);
    float wb = (x1f - x) * (y - y0f);
    float wc = (x - x0f) * (y1f - y);
    float wd = (x - x0f) * (y - y0f);
    const float* base = sf + (size_t)b * CBEV * HBEV * WBEV;
    int c = threadIdx.x;                   // 256 threads = channels
    const float* pc = base + (size_t)c * (HBEV * WBEV);
    float Ia = pc[y0 * WBEV + x0];
    float Ib = pc[y1 * WBEV + x0];
    float Ic = pc[y0 * WBEV + x1];
    float Id = pc[y1 * WBEV + x1];
    g_feats[row * FEAT_DIM + c] = Ia * wa + Ib * wb + Ic * wc + Id * wd;
}

// ---------------- ball query (both radii) + grouping -------------------------
// 256 CTAs x 128 thr; each CTA = 16 keypoints (4 per warp), tiles points in smem.
__global__ void k_group(const float* __restrict__ kp, const float* __restrict__ pxyz,
                        const float* __restrict__ pfeat) {
    __shared__ float sx[2048], sy[2048], sz[2048];
    __shared__ int lst0[16][16], lst1[16][16];
    __shared__ int cnt0[16], cnt1[16];
    int tid = threadIdx.x;
    int b = blockIdx.x >> 7;
    int kflat0 = blockIdx.x * 16;
    if (tid < 16) { cnt0[tid] = 0; cnt1[tid] = 0; }
    int warp = tid >> 5, lane = tid & 31;
    float kx[4], ky[4], kz[4];
#pragma unroll
    for (int u = 0; u < 4; u++) {
        const float* p = kp + (size_t)(kflat0 + warp * 4 + u) * 3;
        kx[u] = p[0]; ky[u] = p[1]; kz[u] = p[2];
    }
    // match reference: python-double radius*radius rounded to f32
    const float R0SQ = (float)(0.4 * 0.4);
    const float R1SQ = (float)(0.8 * 0.8);
    const float* pb = pxyz + (size_t)b * NN * 3;

    for (int t = 0; t < NN; t += 2048) {
        __syncthreads();
        for (int i = tid; i < 2048; i += 128) {
            const float* p = pb + (size_t)(t + i) * 3;
            sx[i] = p[0]; sy[i] = p[1]; sz[i] = p[2];
        }
        __syncthreads();
        for (int j = 0; j < 2048; j += 32) {
            float px = sx[j + lane], py = sy[j + lane], pz = sz[j + lane];
            float d[4];
#pragma unroll
            for (int u = 0; u < 4; u++) {
                float dx = kx[u] - px, dy = ky[u] - py, dz = kz[u] - pz;
                // exact left-to-right, no FMA contraction (match XLA)
                d[u] = __fadd_rn(__fadd_rn(__fmul_rn(dx, dx), __fmul_rn(dy, dy)),
                                 __fmul_rn(dz, dz));
            }
            float m = fminf(fminf(d[0], d[1]), fminf(d[2], d[3]));
            if (__ballot_sync(FULLMASK, m < R1SQ)) {
#pragma unroll
                for (int u = 0; u < 4; u++) {
                    unsigned m1 = __ballot_sync(FULLMASK, d[u] < R1SQ);
                    if (m1) {
                        unsigned m0 = __ballot_sync(FULLMASK, d[u] < R0SQ);
                        if (lane == 0) {
                            int kl = warp * 4 + u;
                            int c = cnt1[kl]; unsigned mm = m1;
                            while (mm && c < 16) {
                                int bit = __ffs(mm) - 1; mm &= mm - 1;
                                lst1[kl][c++] = t + j + bit;
                            }
                            cnt1[kl] = c;
                            c = cnt0[kl]; mm = m0;
                            while (mm && c < 16) {
                                int bit = __ffs(mm) - 1; mm &= mm - 1;
                                lst0[kl][c++] = t + j + bit;
                            }
                            cnt0[kl] = c;
                        }
                    }
                }
            }
        }
    }
    __syncthreads();
    const float* fb = pfeat + (size_t)b * NN;
    for (int it = tid; it < 512; it += 128) {
        int kl = it >> 5;
        int rem = it & 31;
        int scale = rem >> 4;
        int s = rem & 15;
        int kflat = kflat0 + kl;
        int cnt = scale ? cnt1[kl] : cnt0[kl];
        float4 out = make_float4(0.f, 0.f, 0.f, 0.f);
        if (cnt > 0) {
            int idx = (s < cnt) ? (scale ? lst1[kl][s] : lst0[kl][s])
                                : (scale ? lst1[kl][0] : lst0[kl][0]);
            const float* p = pb + (size_t)idx * 3;
            const float* kpp = kp + (size_t)kflat * 3;
            out.x = p[0] - kpp[0];
            out.y = p[1] - kpp[1];
            out.z = p[2] - kpp[2];
            out.w = fb[idx];
        }
        (scale ? g_g1 : g_g0)[(size_t)kflat * 16 + s] = out;
        if (s == 0) {
            if (scale) g_e1[kflat] = (cnt == 0);
            else       g_e0[kflat] = (cnt == 0);
        }
    }
}

// ---------------- MLP layer 0: (S,4) @ W(16,4)^T, store z + stats -----------
__global__ void k_l0(const float* __restrict__ W, int useG1, int accOff) {
    __shared__ float sW[64];
    __shared__ float s_red[32];
    int tid = threadIdx.x;
    if (tid < 64) sW[tid] = W[tid];
    if (tid < 32) s_red[tid] = 0.f;
    __syncthreads();
    const float4* G = useG1 ? g_g1 : g_g0;
    float aS[16], aQ[16];
#pragma unroll
    for (int o = 0; o < 16; o++) { aS[o] = 0.f; aQ[o] = 0.f; }
    int base = blockIdx.x * 1024 + tid;
#pragma unroll
    for (int i = 0; i < 4; i++) {
        int row = base + i * 256;
        float4 g = G[row];
        float zbuf[16];
#pragma unroll
        for (int o = 0; o < 16; o++) {
            float z = g.x * sW[o * 4 + 0] + g.y * sW[o * 4 + 1] +
                      g.z * sW[o * 4 + 2] + g.w * sW[o * 4 + 3];
            zbuf[o] = z;
            aS[o] += z; aQ[o] += z * z;
        }
#pragma unroll
        for (int q = 0; q < 4; q++)
            g_z0[(size_t)row * 4 + q] =
                make_float4(zbuf[q * 4 + 0], zbuf[q * 4 + 1], zbuf[q * 4 + 2], zbuf[q * 4 + 3]);
    }
    int lane = tid & 31;
#pragma unroll
    for (int v = 0; v < 32; v++) {
        float val = (v < 16) ? aS[v] : aQ[v - 16];
        val += __shfl_down_sync(FULLMASK, val, 16);
        val += __shfl_down_sync(FULLMASK, val, 8);
        val += __shfl_down_sync(FULLMASK, val, 4);
        val += __shfl_down_sync(FULLMASK, val, 2);
        val += __shfl_down_sync(FULLMASK, val, 1);
        if (lane == 0) atomicAdd(&s_red[v], val);
    }
    __syncthreads();
    if (tid < 32) atomicAdd(&g_acc[accOff + tid], s_red[tid]);
}

// ---------------- MLP layer 1: bn(z0)->relu -> @ W(C,16)^T, store + stats ---
template <int C>
__global__ void k_l1(const float* __restrict__ gamma, const float* __restrict__ beta,
                     const float* __restrict__ W, int accInOff, int accOutOff) {
    __shared__ float sW[C * 16];
    __shared__ float sA[16], sB[16];
    __shared__ float s_red[2 * C];
    int tid = threadIdx.x;
    for (int i = tid; i < C * 16; i += 256) sW[i] = W[i];
    if (tid < 16) {
        float s = g_acc[accInOff + tid], q = g_acc[accInOff + 16 + tid];
        float mean = s * (1.0f / 65536.0f);
        float var = q * (1.0f / 65536.0f) - mean * mean;
        float sc = gamma[tid] * rsqrtf(var + 1e-5f);
        sA[tid] = sc;
        sB[tid] = beta[tid] - mean * sc;
    }
    if (tid < 2 * C) s_red[tid] = 0.f;
    __syncthreads();
    float aS[C], aQ[C];
#pragma unroll
    for (int o = 0; o < C; o++) { aS[o] = 0.f; aQ[o] = 0.f; }
    int base = blockIdx.x * 1024 + tid;
#pragma unroll
    for (int i = 0; i < 4; i++) {
        int row = base + i * 256;
        float y[16];
#pragma unroll
        for (int c4 = 0; c4 < 4; c4++) {
            float4 x = g_z0[(size_t)row * 4 + c4];
            y[c4 * 4 + 0] = fmaxf(x.x * sA[c4 * 4 + 0] + sB[c4 * 4 + 0], 0.f);
            y[c4 * 4 + 1] = fmaxf(x.y * sA[c4 * 4 + 1] + sB[c4 * 4 + 1], 0.f);
            y[c4 * 4 + 2] = fmaxf(x.z * sA[c4 * 4 + 2] + sB[c4 * 4 + 2], 0.f);
            y[c4 * 4 + 3] = fmaxf(x.w * sA[c4 * 4 + 3] + sB[c4 * 4 + 3], 0.f);
        }
#pragma unroll
        for (int o4 = 0; o4 < C / 4; o4++) {
            float zq[4];
#pragma unroll
            for (int oo = 0; oo < 4; oo++) {
                int o = o4 * 4 + oo;
                float z = 0.f;
#pragma unroll
                for (int c = 0; c < 16; c++) z += y[c] * sW[o * 16 + c];
                zq[oo] = z;
                aS[o] += z; aQ[o] += z * z;
            }
            g_z1[(size_t)row * (C / 4) + o4] = make_float4(zq[0], zq[1], zq[2], zq[3]);
        }
    }
    int lane = tid & 31;
#pragma unroll
    for (int v = 0; v < 2 * C; v++) {
        float val = (v < C) ? aS[v] : aQ[v - C];
        val += __shfl_down_sync(FULLMASK, val, 16);
        val += __shfl_down_sync(FULLMASK, val, 8);
        val += __shfl_down_sync(FULLMASK, val, 4);
        val += __shfl_down_sync(FULLMASK, val, 2);
        val += __shfl_down_sync(FULLMASK, val, 1);
        if (lane == 0) atomicAdd(&s_red[v], val);
    }
    __syncthreads();
    if (tid < 2 * C) atomicAdd(&g_acc[accOutOff + tid], s_red[tid]);
}

// ---------------- bn+relu+maxpool over 16 samples -> feats ------------------
template <int C>
__global__ void k_pool(const float* __restrict__ gamma, const float* __restrict__ beta,
                       int useE1, int accOff, int colbase) {
    int gid = blockIdx.x * 256 + threadIdx.x;     // ROWS*C threads
    int k = gid / C, o = gid - k * C;
    float mean = g_acc[accOff + o] * (1.0f / 65536.0f);
    float var = g_acc[accOff + C + o] * (1.0f / 65536.0f) - mean * mean;
    float a = gamma[o] * rsqrtf(var + 1e-5f);
    float bb = beta[o] - mean * a;
    const float* zp = ((const float*)g_z1) + ((size_t)k * 16) * C + o;
    float mx = 0.f;                               // relu outputs are >= 0
#pragma unroll
    for (int s = 0; s < 16; s++) {
        float v = fmaxf(zp[s * C] * a + bb, 0.f);
        mx = fmaxf(mx, v);
    }
    unsigned char e = useE1 ? g_e1[k] : g_e0[k];
    if (e) mx = 0.f;
    g_feats[(size_t)k * FEAT_DIM + colbase + o] = mx;
}

// ---------------- final GEMM: feats(4096,304) @ Wf(128,304)^T + stats -------
__global__ void k_fgemm(const float* __restrict__ Wf) {
    __shared__ float sF[16 * FEAT_DIM];
    int tid = threadIdx.x;                        // 128 = output channel
    int r0 = blockIdx.x * 16;
    for (int i = tid; i < 16 * FEAT_DIM; i += 128)
        sF[i] = g_feats[(size_t)r0 * FEAT_DIM + i];
    __syncthreads();
    float acc_[16];
#pragma unroll
    for (int r = 0; r < 16; r++) acc_[r] = 0.f;
    const float* wrow = Wf + (size_t)tid * FEAT_DIM;
#pragma unroll 4
    for (int c = 0; c < FEAT_DIM; c++) {
        float w = wrow[c];
#pragma unroll
        for (int r = 0; r < 16; r++) acc_[r] += w * sF[r * FEAT_DIM + c];
    }
    float S = 0.f, Q = 0.f;
#pragma unroll
    for (int r = 0; r < 16; r++) {
        float z = acc_[r];
        g_fz[(size_t)(r0 + r) * OUTC + tid] = z;
        S += z; Q += z * z;
    }
    atomicAdd(&g_acc[160 + tid], S);
    atomicAdd(&g_acc[160 + 128 + tid], Q);
}

// ---------------- final bn + relu -> d_out ----------------------------------
__global__ void k_fbn(const float* __restrict__ gamma, const float* __restrict__ beta,
                      float* __restrict__ out) {
    int gid = blockIdx.x * 256 + threadIdx.x;     // 524288
    int o = gid & 127;
    float mean = g_acc[160 + o] * (1.0f / 4096.0f);
    float var = g_acc[288 + o] * (1.0f / 4096.0f) - mean * mean;
    float v = (g_fz[gid] - mean) * rsqrtf(var + 1e-5f) * gamma[o] + beta[o];
    out[gid] = fmaxf(v, 0.f);
}

// ---------------- launch -----------------------------------------------------
extern "C" void kernel_launch(void* const* d_in, const int* in_sizes, int n_in,
                              void* d_out, int out_size) {
    const float* kp     = (const float*)d_in[0];
    const float* pxyz   = (const float*)d_in[1];
    const float* pfeat  = (const float*)d_in[2];
    const float* sf     = (const float*)d_in[3];
    const int*   stridep= (const int*)d_in[4];
    const float* W0_s0  = (const float*)d_in[5];
    const float* g0_s0  = (const float*)d_in[6];
    const float* b0_s0  = (const float*)d_in[7];
    const float* W1_s0  = (const float*)d_in[8];
    const float* g1_s0  = (const float*)d_in[9];
    const float* b1_s0  = (const float*)d_in[10];
    const float* W0_s1  = (const float*)d_in[11];
    const float* g0_s1  = (const float*)d_in[12];
    const float* b0_s1  = (const float*)d_in[13];
    const float* W1_s1  = (const float*)d_in[14];
    const float* g1_s1  = (const float*)d_in[15];
    const float* b1_s1  = (const float*)d_in[16];
    const float* Wf     = (const float*)d_in[17];
    const float* gf     = (const float*)d_in[18];
    const float* bf     = (const float*)d_in[19];
    (void)in_sizes; (void)n_in; (void)out_size;

    k_zero<<<1, 512>>>();
    k_bev<<<4096, 256>>>(kp, sf, stridep);
    k_group<<<256, 128>>>(kp, pxyz, pfeat);

    // scale 0
    k_l0<<<64, 256>>>(W0_s0, 0, 0);
    k_l1<16><<<64, 256>>>(g0_s0, b0_s0, W1_s0, 0, 32);
    k_pool<16><<<256, 256>>>(g1_s0, b1_s0, 0, 32, 256);

    // scale 1
    k_l0<<<64, 256>>>(W0_s1, 1, 64);
    k_l1<32><<<64, 256>>>(g0_s1, b0_s1, W1_s1, 64, 96);
    k_pool<32><<<512, 256>>>(g1_s1, b1_s1, 1, 96, 272);

    // fused head
    k_fgemm<<<256, 128>>>(Wf);
    k_fbn<<<2048, 256>>>(gf, bf, (float*)d_out);
}

// round 3
// speedup vs baseline: 1.3621x; 1.3621x over previous
#include <cuda_runtime.h>
#include <math.h>

#define FULLMASK 0xffffffffu

#define BB 2
#define KK 2048
#define NN 16384
#define SROWS 65536      // B*K*16 sample-rows
#define ROWS 4096        // B*K
#define CBEV 256
#define HBEV 100
#define WBEV 176
#define FEAT_DIM 304
#define OUTC 128

// ---------------- scratch (device globals; no allocs allowed) ----------------
__device__ float4 g_g0[SROWS];            // grouped scale0: (rel xyz, feat)
__device__ float4 g_g1[SROWS];            // grouped scale1
__device__ unsigned char g_e0[ROWS];
__device__ unsigned char g_e1[ROWS];
__device__ float4 g_z0[SROWS * 4];        // scale0 layer1 pre-BN output (16 ch)
__device__ float4 g_z1[SROWS * 8];        // scale1 layer1 pre-BN output (32 ch)
__device__ float g_feats[ROWS * FEAT_DIM];
__device__ float g_fz[ROWS * OUTC];
__device__ float g_acc[512];              // stat accumulators

// acc layout:
//  [0:14)   s0 grouped moments: sum(4) then M upper-tri(10)
//  [16:30)  s1 grouped moments
//  [32:64)  s0 z1 stats (sum16 @32, sq16 @48)
//  [64:128) s1 z1 stats (sum32 @64, sq32 @96)
//  [160:288) final sum128 ; [288:416) final sq128

// ---------------- BEV bilinear gather -> feats[:, 0:256] (+acc zero) --------
__global__ void k_bev(const float* __restrict__ kp, const float* __restrict__ sf,
                      const int* __restrict__ pstride) {
    int row = blockIdx.x;                  // 0..4095
    if (row == 0) { g_acc[threadIdx.x] = 0.f; g_acc[threadIdx.x + 256] = 0.f; }
    int b = row >> 11;
    float stride = (float)pstride[0];
    float kx = kp[row * 3 + 0];
    float ky = kp[row * 3 + 1];
    float x = (kx - (-70.4f)) / 0.1f / stride;
    float y = (ky - (-40.0f)) / 0.1f / stride;
    int xi = (int)floorf(x), yi = (int)floorf(y);
    int x0 = min(max(xi, 0), WBEV - 1), x1 = min(max(xi + 1, 0), WBEV - 1);
    int y0 = min(max(yi, 0), HBEV - 1), y1 = min(max(yi + 1, 0), HBEV - 1);
    float x0f = (float)x0, x1f = (float)x1, y0f = (float)y0, y1f = (float)y1;
    float wa = (x1f - x) * (y1f - y);
    float wb = (x1f - x) * (y - y0f);
    float wc = (x - x0f) * (y1f - y);
    float wd = (x - x0f) * (y - y0f);
    const float* base = sf + (size_t)b * CBEV * HBEV * WBEV;
    int c = threadIdx.x;                   // 256 threads = channels
    const float* pc = base + (size_t)c * (HBEV * WBEV);
    float Ia = __ldg(pc + y0 * WBEV + x0);
    float Ib = __ldg(pc + y1 * WBEV + x0);
    float Ic = __ldg(pc + y0 * WBEV + x1);
    float Id = __ldg(pc + y1 * WBEV + x1);
    g_feats[row * FEAT_DIM + c] = Ia * wa + Ib * wb + Ic * wc + Id * wd;
}

// ---------------- ball query (both radii) + grouping -------------------------
__global__ void k_group(const float* __restrict__ kp, const float* __restrict__ pxyz,
                        const float* __restrict__ pfeat) {
    __shared__ float sx[2048], sy[2048], sz[2048];
    __shared__ int lst0[16][16], lst1[16][16];
    __shared__ int cnt0[16], cnt1[16];
    int tid = threadIdx.x;
    int b = blockIdx.x >> 7;
    int kflat0 = blockIdx.x * 16;
    if (tid < 16) { cnt0[tid] = 0; cnt1[tid] = 0; }
    int warp = tid >> 5, lane = tid & 31;
    float kx[4], ky[4], kz[4];
#pragma unroll
    for (int u = 0; u < 4; u++) {
        const float* p = kp + (size_t)(kflat0 + warp * 4 + u) * 3;
        kx[u] = p[0]; ky[u] = p[1]; kz[u] = p[2];
    }
    const float R0SQ = (float)(0.4 * 0.4);
    const float R1SQ = (float)(0.8 * 0.8);
    const float* pb = pxyz + (size_t)b * NN * 3;

    for (int t = 0; t < NN; t += 2048) {
        __syncthreads();
        for (int i = tid; i < 2048; i += 128) {
            const float* p = pb + (size_t)(t + i) * 3;
            sx[i] = p[0]; sy[i] = p[1]; sz[i] = p[2];
        }
        __syncthreads();
        for (int j = 0; j < 2048; j += 32) {
            float px = sx[j + lane], py = sy[j + lane], pz = sz[j + lane];
            float d[4];
#pragma unroll
            for (int u = 0; u < 4; u++) {
                float dx = kx[u] - px, dy = ky[u] - py, dz = kz[u] - pz;
                d[u] = __fadd_rn(__fadd_rn(__fmul_rn(dx, dx), __fmul_rn(dy, dy)),
                                 __fmul_rn(dz, dz));
            }
            float m = fminf(fminf(d[0], d[1]), fminf(d[2], d[3]));
            if (__ballot_sync(FULLMASK, m < R1SQ)) {
#pragma unroll
                for (int u = 0; u < 4; u++) {
                    unsigned m1 = __ballot_sync(FULLMASK, d[u] < R1SQ);
                    if (m1) {
                        unsigned m0 = __ballot_sync(FULLMASK, d[u] < R0SQ);
                        if (lane == 0) {
                            int kl = warp * 4 + u;
                            int c = cnt1[kl]; unsigned mm = m1;
                            while (mm && c < 16) {
                                int bit = __ffs(mm) - 1; mm &= mm - 1;
                                lst1[kl][c++] = t + j + bit;
                            }
                            cnt1[kl] = c;
                            c = cnt0[kl]; mm = m0;
                            while (mm && c < 16) {
                                int bit = __ffs(mm) - 1; mm &= mm - 1;
                                lst0[kl][c++] = t + j + bit;
                            }
                            cnt0[kl] = c;
                        }
                    }
                }
            }
        }
    }
    __syncthreads();
    const float* fb = pfeat + (size_t)b * NN;
    for (int it = tid; it < 512; it += 128) {
        int kl = it >> 5;
        int rem = it & 31;
        int scale = rem >> 4;
        int s = rem & 15;
        int kflat = kflat0 + kl;
        int cnt = scale ? cnt1[kl] : cnt0[kl];
        float4 out = make_float4(0.f, 0.f, 0.f, 0.f);
        if (cnt > 0) {
            int idx = (s < cnt) ? (scale ? lst1[kl][s] : lst0[kl][s])
                                : (scale ? lst1[kl][0] : lst0[kl][0]);
            const float* p = pb + (size_t)idx * 3;
            const float* kpp = kp + (size_t)kflat * 3;
            out.x = p[0] - kpp[0];
            out.y = p[1] - kpp[1];
            out.z = p[2] - kpp[2];
            out.w = fb[idx];
        }
        (scale ? g_g1 : g_g0)[(size_t)kflat * 16 + s] = out;
        if (s == 0) {
            if (scale) g_e1[kflat] = (cnt == 0);
            else       g_e0[kflat] = (cnt == 0);
        }
    }
}

// ---------------- grouped-data moments (both scales) -------------------------
// sum(4) + upper-tri second moments(10) per scale -> g_acc[0..14) / [16..30)
__global__ void k_moms() {
    int tid = threadIdx.x;
    int gid = blockIdx.x * 256 + tid;        // 64 blocks x 256 = 16384 threads
    float a[28];
#pragma unroll
    for (int v = 0; v < 28; v++) a[v] = 0.f;
#pragma unroll
    for (int sc = 0; sc < 2; sc++) {
        const float4* G = sc ? g_g1 : g_g0;
        float* p = a + sc * 14;
        for (int r = gid; r < SROWS; r += 16384) {
            float4 g = G[r];
            p[0] += g.x; p[1] += g.y; p[2] += g.z; p[3] += g.w;
            p[4] += g.x * g.x; p[5] += g.x * g.y; p[6] += g.x * g.z; p[7] += g.x * g.w;
            p[8] += g.y * g.y; p[9] += g.y * g.z; p[10] += g.y * g.w;
            p[11] += g.z * g.z; p[12] += g.z * g.w; p[13] += g.w * g.w;
        }
    }
    int lane = tid & 31;
#pragma unroll
    for (int v = 0; v < 28; v++) {
        float val = a[v];
        val += __shfl_down_sync(FULLMASK, val, 16);
        val += __shfl_down_sync(FULLMASK, val, 8);
        val += __shfl_down_sync(FULLMASK, val, 4);
        val += __shfl_down_sync(FULLMASK, val, 2);
        val += __shfl_down_sync(FULLMASK, val, 1);
        if (lane == 0) atomicAdd(&g_acc[(v < 14) ? v : (v - 14 + 16)], val);
    }
}

// ---------------- fused MLP: z0 on-the-fly, bn0 analytic, z1 + stats --------
template <int C>
__global__ void __launch_bounds__(256) k_mlp(
        const float* __restrict__ W0, const float* __restrict__ gamma0,
        const float* __restrict__ beta0, const float* __restrict__ W1,
        const float4* __restrict__ Gin, float4* __restrict__ Zout,
        int momOff, int accOutOff) {
    __shared__ float sW0[64];
    __shared__ float sW1[C * 16];
    __shared__ float sA[16], sB[16];
    __shared__ float s_red[2 * C];
    int tid = threadIdx.x;
    if (tid < 64) sW0[tid] = W0[tid];
    for (int i = tid; i < C * 16; i += 256) sW1[i] = W1[i];
    if (tid < 2 * C) s_red[tid] = 0.f;
    __syncthreads();
    if (tid < 16) {
        // analytic bn0 stats from grouped moments
        float w0 = sW0[tid * 4 + 0], w1 = sW0[tid * 4 + 1];
        float w2 = sW0[tid * 4 + 2], w3 = sW0[tid * 4 + 3];
        const float* m = &g_acc[momOff];
        float mean = (w0 * m[0] + w1 * m[1] + w2 * m[2] + w3 * m[3]) * (1.0f / 65536.0f);
        float e2 = w0 * w0 * m[4] + w1 * w1 * m[8] + w2 * w2 * m[11] + w3 * w3 * m[13]
                 + 2.f * (w0 * w1 * m[5] + w0 * w2 * m[6] + w0 * w3 * m[7]
                        + w1 * w2 * m[9] + w1 * w3 * m[10] + w2 * w3 * m[12]);
        e2 *= (1.0f / 65536.0f);
        float var = e2 - mean * mean;
        float sc = gamma0[tid] * rsqrtf(var + 1e-5f);
        sA[tid] = sc;
        sB[tid] = beta0[tid] - mean * sc;
    }
    __syncthreads();
    float aS[C], aQ[C];
#pragma unroll
    for (int o = 0; o < C; o++) { aS[o] = 0.f; aQ[o] = 0.f; }
    int row = blockIdx.x * 256 + tid;        // 256 blocks
    {
        float4 g = Gin[row];
        float y[16];
#pragma unroll
        for (int o = 0; o < 16; o++) {
            float z = g.x * sW0[o * 4 + 0] + g.y * sW0[o * 4 + 1] +
                      g.z * sW0[o * 4 + 2] + g.w * sW0[o * 4 + 3];
            y[o] = fmaxf(z * sA[o] + sB[o], 0.f);
        }
#pragma unroll
        for (int o4 = 0; o4 < C / 4; o4++) {
            float zq[4];
#pragma unroll
            for (int oo = 0; oo < 4; oo++) {
                int o = o4 * 4 + oo;
                float z = 0.f;
#pragma unroll
                for (int c = 0; c < 16; c++) z += y[c] * sW1[o * 16 + c];
                zq[oo] = z;
                aS[o] += z; aQ[o] += z * z;
            }
            Zout[(size_t)row * (C / 4) + o4] = make_float4(zq[0], zq[1], zq[2], zq[3]);
        }
    }
    int lane = tid & 31;
#pragma unroll
    for (int v = 0; v < 2 * C; v++) {
        float val = (v < C) ? aS[v] : aQ[v - C];
        val += __shfl_down_sync(FULLMASK, val, 16);
        val += __shfl_down_sync(FULLMASK, val, 8);
        val += __shfl_down_sync(FULLMASK, val, 4);
        val += __shfl_down_sync(FULLMASK, val, 2);
        val += __shfl_down_sync(FULLMASK, val, 1);
        if (lane == 0) atomicAdd(&s_red[v], val);
    }
    __syncthreads();
    if (tid < 2 * C) atomicAdd(&g_acc[accOutOff + tid], s_red[tid]);
}

// ---------------- bn+relu+maxpool over 16 samples -> feats ------------------
template <int C>
__global__ void k_pool(const float* __restrict__ gamma, const float* __restrict__ beta,
                       const float* __restrict__ Z, const unsigned char* __restrict__ E,
                       int accOff, int colbase) {
    int gid = blockIdx.x * 256 + threadIdx.x;     // ROWS*C threads
    int k = gid / C, o = gid - k * C;
    float mean = g_acc[accOff + o] * (1.0f / 65536.0f);
    float var = g_acc[accOff + C + o] * (1.0f / 65536.0f) - mean * mean;
    float a = gamma[o] * rsqrtf(var + 1e-5f);
    float bb = beta[o] - mean * a;
    const float* zp = Z + ((size_t)k * 16) * C + o;
    float mx = 0.f;
#pragma unroll
    for (int s = 0; s < 16; s++) {
        float v = fmaxf(zp[s * C] * a + bb, 0.f);
        mx = fmaxf(mx, v);
    }
    if (E[k]) mx = 0.f;
    g_feats[(size_t)k * FEAT_DIM + colbase + o] = mx;
}

// ---------------- final GEMM: feats(4096,304) @ Wf(128,304)^T + stats -------
__global__ void __launch_bounds__(256) k_fgemm(const float* __restrict__ Wf) {
    __shared__ float sF[32 * FEAT_DIM];          // 38.9 KB
    int tid = threadIdx.x;
    int r0 = blockIdx.x * 32;                    // 128 CTAs
    const float4* src = (const float4*)(g_feats + (size_t)r0 * FEAT_DIM);
    float4* dst = (float4*)sF;
    for (int i = tid; i < 32 * (FEAT_DIM / 4); i += 256) dst[i] = src[i];
    __syncthreads();
    int o = tid & 127;
    int rh = tid >> 7;                           // 0/1 -> rows rh*16..rh*16+15
    float acc_[16];
#pragma unroll
    for (int r = 0; r < 16; r++) acc_[r] = 0.f;
    const float4* wrow = (const float4*)(Wf + (size_t)o * FEAT_DIM);
    const float4* fbase = (const float4*)sF + (size_t)(rh * 16) * (FEAT_DIM / 4);
#pragma unroll 2
    for (int c4 = 0; c4 < FEAT_DIM / 4; c4++) {
        float4 w = __ldg(wrow + c4);
#pragma unroll
        for (int r = 0; r < 16; r++) {
            float4 f = fbase[(size_t)r * (FEAT_DIM / 4) + c4];
            acc_[r] += w.x * f.x + w.y * f.y + w.z * f.z + w.w * f.w;
        }
    }
    float S = 0.f, Q = 0.f;
#pragma unroll
    for (int r = 0; r < 16; r++) {
        float z = acc_[r];
        g_fz[(size_t)(r0 + rh * 16 + r) * OUTC + o] = z;
        S += z; Q += z * z;
    }
    atomicAdd(&g_acc[160 + o], S);
    atomicAdd(&g_acc[288 + o], Q);
}

// ---------------- final bn + relu -> d_out ----------------------------------
__global__ void k_fbn(const float* __restrict__ gamma, const float* __restrict__ beta,
                      float* __restrict__ out) {
    int gid = blockIdx.x * 256 + threadIdx.x;     // 524288
    int o = gid & 127;
    float mean = g_acc[160 + o] * (1.0f / 4096.0f);
    float var = g_acc[288 + o] * (1.0f / 4096.0f) - mean * mean;
    float v = (g_fz[gid] - mean) * rsqrtf(var + 1e-5f) * gamma[o] + beta[o];
    out[gid] = fmaxf(v, 0.f);
}

// ---------------- launch -----------------------------------------------------
extern "C" void kernel_launch(void* const* d_in, const int* in_sizes, int n_in,
                              void* d_out, int out_size) {
    const float* kp     = (const float*)d_in[0];
    const float* pxyz   = (const float*)d_in[1];
    const float* pfeat  = (const float*)d_in[2];
    const float* sf     = (const float*)d_in[3];
    const int*   stridep= (const int*)d_in[4];
    const float* W0_s0  = (const float*)d_in[5];
    const float* g0_s0  = (const float*)d_in[6];
    const float* b0_s0  = (const float*)d_in[7];
    const float* W1_s0  = (const float*)d_in[8];
    const float* g1_s0  = (const float*)d_in[9];
    const float* b1_s0  = (const float*)d_in[10];
    const float* W0_s1  = (const float*)d_in[11];
    const float* g0_s1  = (const float*)d_in[12];
    const float* b0_s1  = (const float*)d_in[13];
    const float* W1_s1  = (const float*)d_in[14];
    const float* g1_s1  = (const float*)d_in[15];
    const float* b1_s1  = (const float*)d_in[16];
    const float* Wf     = (const float*)d_in[17];
    const float* gf     = (const float*)d_in[18];
    const float* bf     = (const float*)d_in[19];
    (void)in_sizes; (void)n_in; (void)out_size;

    float4* z0p; cudaGetSymbolAddress((void**)&z0p, g_z0);
    float4* z1p; cudaGetSymbolAddress((void**)&z1p, g_z1);
    float4* g0p; cudaGetSymbolAddress((void**)&g0p, g_g0);
    float4* g1p; cudaGetSymbolAddress((void**)&g1p, g_g1);
    unsigned char* e0p; cudaGetSymbolAddress((void**)&e0p, g_e0);
    unsigned char* e1p; cudaGetSymbolAddress((void**)&e1p, g_e1);

    k_bev<<<4096, 256>>>(kp, sf, stridep);
    k_group<<<256, 128>>>(kp, pxyz, pfeat);
    k_moms<<<64, 256>>>();

    k_mlp<16><<<256, 256>>>(W0_s0, g0_s0, b0_s0, W1_s0, g0p, z0p, 0, 32);
    k_mlp<32><<<256, 256>>>(W0_s1, g0_s1, b0_s1, W1_s1, g1p, z1p, 16, 64);

    k_pool<16><<<256, 256>>>(g1_s0, b1_s0, (const float*)z0p, e0p, 32, 256);
    k_pool<32><<<512, 256>>>(g1_s1, b1_s1, (const float*)z1p, e1p, 64, 272);

    k_fgemm<<<128, 256>>>(Wf);
    k_fbn<<<2048, 256>>>(gf, bf, (float*)d_out);
}

// round 4
// speedup vs baseline: 2.3079x; 1.6943x over previous
#include <cuda_runtime.h>
#include <math.h>

#define FULLMASK 0xffffffffu

#define BB 2
#define KK 2048
#define NN 16384
#define SROWS 65536      // B*K*16 sample-rows
#define ROWS 4096        // B*K
#define CBEV 256
#define HBEV 100
#define WBEV 176
#define FEAT_DIM 304
#define OUTC 128

// spatial hash for ball query
#define NXC 89
#define NYC 51
#define NCELL (NXC * NYC)    // 4539 per batch
#define CAP 64

// ---------------- scratch (device globals; no allocs allowed) ----------------
__device__ float4 g_g0[SROWS];            // grouped scale0: (rel xyz, feat)
__device__ float4 g_g1[SROWS];            // grouped scale1
__device__ unsigned char g_e0[ROWS];
__device__ unsigned char g_e1[ROWS];
__device__ float4 g_z0[SROWS * 4];        // scale0 layer1 pre-BN output (16 ch)
__device__ float4 g_z1[SROWS * 8];        // scale1 layer1 pre-BN output (32 ch)
__device__ float g_feats[ROWS * FEAT_DIM];
__device__ float g_fz[ROWS * OUTC];
__device__ float g_acc[512];              // stat accumulators
__device__ float4 g_cells[2 * NCELL * CAP];  // (x,y,z,idx-as-int)
__device__ int g_ccnt[2 * NCELL];

// acc layout:
//  [0:14)   s0 grouped moments: sum(4) then M upper-tri(10)
//  [16:30)  s1 grouped moments
//  [32:64)  s0 z stats (sum16 @32, sq16 @48)
//  [64:128) s1 z stats (sum32 @64, sq32 @96)
//  [160:288) final sum128 ; [288:416) final sq128

// ---------------- BEV bilinear gather -> feats[:, 0:256] --------------------
__global__ void k_bev(const float* __restrict__ kp, const float* __restrict__ sf,
                      const int* __restrict__ pstride) {
    int row = blockIdx.x;                  // 0..4095
    int b = row >> 11;
    float stride = (float)pstride[0];
    float kx = kp[row * 3 + 0];
    float ky = kp[row * 3 + 1];
    float x = (kx - (-70.4f)) / 0.1f / stride;
    float y = (ky - (-40.0f)) / 0.1f / stride;
    int xi = (int)floorf(x), yi = (int)floorf(y);
    int x0 = min(max(xi, 0), WBEV - 1), x1 = min(max(xi + 1, 0), WBEV - 1);
    int y0 = min(max(yi, 0), HBEV - 1), y1 = min(max(yi + 1, 0), HBEV - 1);
    float x0f = (float)x0, x1f = (float)x1, y0f = (float)y0, y1f = (float)y1;
    float wa = (x1f - x) * (y1f - y);
    float wb = (x1f - x) * (y - y0f);
    float wc = (x - x0f) * (y1f - y);
    float wd = (x - x0f) * (y - y0f);
    const float* base = sf + (size_t)b * CBEV * HBEV * WBEV;
    int c = threadIdx.x;                   // 256 threads = channels
    const float* pc = base + (size_t)c * (HBEV * WBEV);
    float Ia = __ldg(pc + y0 * WBEV + x0);
    float Ib = __ldg(pc + y1 * WBEV + x0);
    float Ic = __ldg(pc + y0 * WBEV + x1);
    float Id = __ldg(pc + y1 * WBEV + x1);
    g_feats[row * FEAT_DIM + c] = Ia * wa + Ib * wb + Ic * wc + Id * wd;
}

// ---------------- scatter points into 1.6m xy-cells --------------------------
__global__ void k_scatter(const float* __restrict__ pxyz) {
    int gid = blockIdx.x * 256 + threadIdx.x;     // 32768
    int b = gid >> 14;
    const float* p = pxyz + (size_t)gid * 3;
    float x = p[0], y = p[1], z = p[2];
    int cx = min(max((int)floorf((x + 70.4f) * 0.625f), 0), NXC - 1);
    int cy = min(max((int)floorf((y + 40.0f) * 0.625f), 0), NYC - 1);
    int cell = b * NCELL + cy * NXC + cx;
    int slot = atomicAdd(&g_ccnt[cell], 1);
    if (slot < CAP)
        g_cells[(size_t)cell * CAP + slot] =
            make_float4(x, y, z, __int_as_float(gid & 16383));
}

// ---------------- ball query via cells: warp per keypoint --------------------
__global__ void __launch_bounds__(256) k_group2(
        const float* __restrict__ kp, const float* __restrict__ pxyz,
        const float* __restrict__ pfeat) {
    __shared__ int s_hits[8][32];
    __shared__ int s_cnt[8];
    int wib = threadIdx.x >> 5, lane = threadIdx.x & 31;
    int kpid = blockIdx.x * 8 + wib;              // 512 CTAs x 8 warps = 4096
    int b = kpid >> 11;
    float kx = kp[kpid * 3 + 0], ky = kp[kpid * 3 + 1], kz = kp[kpid * 3 + 2];
    if (lane == 0) s_cnt[wib] = 0;
    __syncwarp();
    const float R0SQ = (float)(0.4 * 0.4);
    const float R1SQ = (float)(0.8 * 0.8);
    int cx0 = min(max((int)floorf((kx - 0.81f + 70.4f) * 0.625f), 0), NXC - 1);
    int cx1 = min(max((int)floorf((kx + 0.81f + 70.4f) * 0.625f), 0), NXC - 1);
    int cy0 = min(max((int)floorf((ky - 0.81f + 40.0f) * 0.625f), 0), NYC - 1);
    int cy1 = min(max((int)floorf((ky + 0.81f + 40.0f) * 0.625f), 0), NYC - 1);
    for (int cy = cy0; cy <= cy1; cy++) {
        for (int cx = cx0; cx <= cx1; cx++) {
            int cell = b * NCELL + cy * NXC + cx;
            int cnt = min(g_ccnt[cell], CAP);
            const float4* bp = &g_cells[(size_t)cell * CAP];
            for (int i = lane; i < cnt; i += 32) {
                float4 p = bp[i];
                float dx = kx - p.x, dy = ky - p.y, dz = kz - p.z;
                float d = __fadd_rn(__fadd_rn(__fmul_rn(dx, dx), __fmul_rn(dy, dy)),
                                    __fmul_rn(dz, dz));
                if (d < R1SQ) {
                    int pos = atomicAdd(&s_cnt[wib], 1);
                    if (pos < 32)
                        s_hits[wib][pos] = (__float_as_int(p.w) << 1) | (d < R0SQ ? 1 : 0);
                }
            }
        }
    }
    __syncwarp();
    int cnt = min(s_cnt[wib], 32);
    if (lane == 0 && cnt > 1) {            // insertion sort by (idx<<1|r0) = idx order
        for (int i = 1; i < cnt; i++) {
            int key = s_hits[wib][i];
            int j = i - 1;
            while (j >= 0 && s_hits[wib][j] > key) { s_hits[wib][j + 1] = s_hits[wib][j]; j--; }
            s_hits[wib][j + 1] = key;
        }
    }
    __syncwarp();
    int ent = (lane < cnt) ? s_hits[wib][lane] : 0;
    unsigned mask0 = __ballot_sync(FULLMASK, (lane < cnt) && (ent & 1));
    int n0 = __popc(mask0);
    int scale = (lane < 16) ? 1 : 0;
    int s = scale ? lane : (lane - 16);
    int myidx = -1;
    if (scale) {
        if (cnt > 0) myidx = ((s < cnt) ? s_hits[wib][s] : s_hits[wib][0]) >> 1;
    } else {
        if (n0 > 0) {
            int target = (s < n0) ? s : 0;
            unsigned m = mask0;
            for (int t = 0; t < target; t++) m &= m - 1;
            int pos = __ffs(m) - 1;
            myidx = s_hits[wib][pos] >> 1;
        }
    }
    float4 out = make_float4(0.f, 0.f, 0.f, 0.f);
    if (myidx >= 0) {
        const float* pp = pxyz + ((size_t)b * NN + myidx) * 3;
        out.x = pp[0] - kx;
        out.y = pp[1] - ky;
        out.z = pp[2] - kz;
        out.w = pfeat[(size_t)b * NN + myidx];
    }
    if (scale) g_g1[(size_t)kpid * 16 + s] = out;
    else       g_g0[(size_t)kpid * 16 + s] = out;
    if (s == 0) {
        if (scale) g_e1[kpid] = (cnt == 0);
        else       g_e0[kpid] = (n0 == 0);
    }
}

// ---------------- grouped-data moments (both scales) -------------------------
__global__ void k_moms() {
    int tid = threadIdx.x;
    int gid = blockIdx.x * 256 + tid;        // 64 blocks x 256 = 16384 threads
    float a[28];
#pragma unroll
    for (int v = 0; v < 28; v++) a[v] = 0.f;
#pragma unroll
    for (int sc = 0; sc < 2; sc++) {
        const float4* G = sc ? g_g1 : g_g0;
        float* p = a + sc * 14;
        for (int r = gid; r < SROWS; r += 16384) {
            float4 g = G[r];
            p[0] += g.x; p[1] += g.y; p[2] += g.z; p[3] += g.w;
            p[4] += g.x * g.x; p[5] += g.x * g.y; p[6] += g.x * g.z; p[7] += g.x * g.w;
            p[8] += g.y * g.y; p[9] += g.y * g.z; p[10] += g.y * g.w;
            p[11] += g.z * g.z; p[12] += g.z * g.w; p[13] += g.w * g.w;
        }
    }
    int lane = tid & 31;
#pragma unroll
    for (int v = 0; v < 28; v++) {
        float val = a[v];
        val += __shfl_down_sync(FULLMASK, val, 16);
        val += __shfl_down_sync(FULLMASK, val, 8);
        val += __shfl_down_sync(FULLMASK, val, 4);
        val += __shfl_down_sync(FULLMASK, val, 2);
        val += __shfl_down_sync(FULLMASK, val, 1);
        if (lane == 0) atomicAdd(&g_acc[(v < 14) ? v : (v - 14 + 16)], val);
    }
}

// ---------------- fused MLP: pure stream, bn0 analytic ----------------------
template <int C>
__global__ void __launch_bounds__(256) k_mlp(
        const float* __restrict__ W0, const float* __restrict__ gamma0,
        const float* __restrict__ beta0, const float* __restrict__ W1,
        const float4* __restrict__ Gin, float4* __restrict__ Zout, int momOff) {
    __shared__ float sW0[64];
    __shared__ float sW1[C * 16];
    __shared__ float sA[16], sB[16];
    int tid = threadIdx.x;
    if (tid < 64) sW0[tid] = W0[tid];
    for (int i = tid; i < C * 16; i += 256) sW1[i] = W1[i];
    __syncthreads();
    if (tid < 16) {
        float w0 = sW0[tid * 4 + 0], w1 = sW0[tid * 4 + 1];
        float w2 = sW0[tid * 4 + 2], w3 = sW0[tid * 4 + 3];
        const float* m = &g_acc[momOff];
        float mean = (w0 * m[0] + w1 * m[1] + w2 * m[2] + w3 * m[3]) * (1.0f / 65536.0f);
        float e2 = w0 * w0 * m[4] + w1 * w1 * m[8] + w2 * w2 * m[11] + w3 * w3 * m[13]
                 + 2.f * (w0 * w1 * m[5] + w0 * w2 * m[6] + w0 * w3 * m[7]
                        + w1 * w2 * m[9] + w1 * w3 * m[10] + w2 * w3 * m[12]);
        e2 *= (1.0f / 65536.0f);
        float var = e2 - mean * mean;
        float sc = gamma0[tid] * rsqrtf(var + 1e-5f);
        sA[tid] = sc;
        sB[tid] = beta0[tid] - mean * sc;
    }
    __syncthreads();
    int row = blockIdx.x * 256 + tid;        // 256 blocks
    float4 g = Gin[row];
    float y[16];
#pragma unroll
    for (int o = 0; o < 16; o++) {
        float z = g.x * sW0[o * 4 + 0] + g.y * sW0[o * 4 + 1] +
                  g.z * sW0[o * 4 + 2] + g.w * sW0[o * 4 + 3];
        y[o] = fmaxf(z * sA[o] + sB[o], 0.f);
    }
#pragma unroll
    for (int o4 = 0; o4 < C / 4; o4++) {
        float zq[4];
#pragma unroll
        for (int oo = 0; oo < 4; oo++) {
            int o = o4 * 4 + oo;
            float z = 0.f;
#pragma unroll
            for (int c = 0; c < 16; c++) z += y[c] * sW1[o * 16 + c];
            zq[oo] = z;
        }
        Zout[(size_t)row * (C / 4) + o4] = make_float4(zq[0], zq[1], zq[2], zq[3]);
    }
}

// ---------------- z stats: lane == channel, zero shuffles --------------------
__global__ void __launch_bounds__(256) k_zstats() {
    __shared__ float r1[64], r0[32];
    int tid = threadIdx.x;
    int gt = blockIdx.x * 256 + tid;          // 128 CTAs -> 32768 threads
    if (tid < 64) r1[tid] = 0.f;
    if (tid < 32) r0[tid] = 0.f;
    __syncthreads();
    const float* Z1 = (const float*)g_z1;     // 2M floats, channel = f & 31
    float s = 0.f, q = 0.f;
    for (int f = gt; f < SROWS * 32; f += 32768) {
        float v = Z1[f];
        s += v; q += v * v;
    }
    atomicAdd(&r1[tid & 31], s);
    atomicAdd(&r1[32 + (tid & 31)], q);
    const float* Z0 = (const float*)g_z0;     // 1M floats, channel = f & 15
    s = 0.f; q = 0.f;
    for (int f = gt; f < SROWS * 16; f += 32768) {
        float v = Z0[f];
        s += v; q += v * v;
    }
    atomicAdd(&r0[tid & 15], s);
    atomicAdd(&r0[16 + (tid & 15)], q);
    __syncthreads();
    if (tid < 64) atomicAdd(&g_acc[64 + tid], r1[tid]);   // s1: sum32@64, sq32@96
    else if (tid < 96) atomicAdd(&g_acc[32 + tid - 64], r0[tid - 64]); // s0 @32/@48
}

// ---------------- bn+relu+maxpool over 16 samples -> feats ------------------
template <int C>
__global__ void k_pool(const float* __restrict__ gamma, const float* __restrict__ beta,
                       const float* __restrict__ Z, const unsigned char* __restrict__ E,
                       int accOff, int colbase) {
    int gid = blockIdx.x * 256 + threadIdx.x;     // ROWS*C threads
    int k = gid / C, o = gid - k * C;
    float mean = g_acc[accOff + o] * (1.0f / 65536.0f);
    float var = g_acc[accOff + C + o] * (1.0f / 65536.0f) - mean * mean;
    float a = gamma[o] * rsqrtf(var + 1e-5f);
    float bb = beta[o] - mean * a;
    const float* zp = Z + ((size_t)k * 16) * C + o;
    float mx = 0.f;
#pragma unroll
    for (int s = 0; s < 16; s++) {
        float v = fmaxf(zp[s * C] * a + bb, 0.f);
        mx = fmaxf(mx, v);
    }
    if (E[k]) mx = 0.f;
    g_feats[(size_t)k * FEAT_DIM + colbase + o] = mx;
}

// ---------------- final GEMM: feats(4096,304) @ Wf(128,304)^T + stats -------
__global__ void __launch_bounds__(256) k_fgemm(const float* __restrict__ Wf) {
    __shared__ float sF[32 * FEAT_DIM];          // 38.9 KB
    int tid = threadIdx.x;
    int r0 = blockIdx.x * 32;                    // 128 CTAs
    const float4* src = (const float4*)(g_feats + (size_t)r0 * FEAT_DIM);
    float4* dst = (float4*)sF;
    for (int i = tid; i < 32 * (FEAT_DIM / 4); i += 256) dst[i] = src[i];
    __syncthreads();
    int o = tid & 127;
    int rh = tid >> 7;
    float acc_[16];
#pragma unroll
    for (int r = 0; r < 16; r++) acc_[r] = 0.f;
    const float4* wrow = (const float4*)(Wf + (size_t)o * FEAT_DIM);
    const float4* fbase = (const float4*)sF + (size_t)(rh * 16) * (FEAT_DIM / 4);
#pragma unroll 2
    for (int c4 = 0; c4 < FEAT_DIM / 4; c4++) {
        float4 w = __ldg(wrow + c4);
#pragma unroll
        for (int r = 0; r < 16; r++) {
            float4 f = fbase[(size_t)r * (FEAT_DIM / 4) + c4];
            acc_[r] += w.x * f.x + w.y * f.y + w.z * f.z + w.w * f.w;
        }
    }
    float S = 0.f, Q = 0.f;
#pragma unroll
    for (int r = 0; r < 16; r++) {
        float z = acc_[r];
        g_fz[(size_t)(r0 + rh * 16 + r) * OUTC + o] = z;
        S += z; Q += z * z;
    }
    atomicAdd(&g_acc[160 + o], S);
    atomicAdd(&g_acc[288 + o], Q);
}

// ---------------- final bn + relu -> d_out ----------------------------------
__global__ void k_fbn(const float* __restrict__ gamma, const float* __restrict__ beta,
                      float* __restrict__ out) {
    int gid = blockIdx.x * 256 + threadIdx.x;     // 524288
    int o = gid & 127;
    float mean = g_acc[160 + o] * (1.0f / 4096.0f);
    float var = g_acc[288 + o] * (1.0f / 4096.0f) - mean * mean;
    float v = (g_fz[gid] - mean) * rsqrtf(var + 1e-5f) * gamma[o] + beta[o];
    out[gid] = fmaxf(v, 0.f);
}

// ---------------- launch -----------------------------------------------------
extern "C" void kernel_launch(void* const* d_in, const int* in_sizes, int n_in,
                              void* d_out, int out_size) {
    const float* kp     = (const float*)d_in[0];
    const float* pxyz   = (const float*)d_in[1];
    const float* pfeat  = (const float*)d_in[2];
    const float* sf     = (const float*)d_in[3];
    const int*   stridep= (const int*)d_in[4];
    const float* W0_s0  = (const float*)d_in[5];
    const float* g0_s0  = (const float*)d_in[6];
    const float* b0_s0  = (const float*)d_in[7];
    const float* W1_s0  = (const float*)d_in[8];
    const float* g1_s0  = (const float*)d_in[9];
    const float* b1_s0  = (const float*)d_in[10];
    const float* W0_s1  = (const float*)d_in[11];
    const float* g0_s1  = (const float*)d_in[12];
    const float* b0_s1  = (const float*)d_in[13];
    const float* W1_s1  = (const float*)d_in[14];
    const float* g1_s1  = (const float*)d_in[15];
    const float* b1_s1  = (const float*)d_in[16];
    const float* Wf     = (const float*)d_in[17];
    const float* gf     = (const float*)d_in[18];
    const float* bf     = (const float*)d_in[19];
    (void)in_sizes; (void)n_in; (void)out_size;

    float4* z0p; cudaGetSymbolAddress((void**)&z0p, g_z0);
    float4* z1p; cudaGetSymbolAddress((void**)&z1p, g_z1);
    float4* g0p; cudaGetSymbolAddress((void**)&g0p, g_g0);
    float4* g1p; cudaGetSymbolAddress((void**)&g1p, g_g1);
    unsigned char* e0p; cudaGetSymbolAddress((void**)&e0p, g_e0);
    unsigned char* e1p; cudaGetSymbolAddress((void**)&e1p, g_e1);
    void* accp; cudaGetSymbolAddress(&accp, g_acc);
    void* ccntp; cudaGetSymbolAddress(&ccntp, g_ccnt);

    cudaMemsetAsync(accp, 0, 512 * sizeof(float));
    cudaMemsetAsync(ccntp, 0, 2 * NCELL * sizeof(int));

    k_bev<<<4096, 256>>>(kp, sf, stridep);
    k_scatter<<<128, 256>>>(pxyz);
    k_group2<<<512, 256>>>(kp, pxyz, pfeat);
    k_moms<<<64, 256>>>();

    k_mlp<16><<<256, 256>>>(W0_s0, g0_s0, b0_s0, W1_s0, g0p, z0p, 0);
    k_mlp<32><<<256, 256>>>(W0_s1, g0_s1, b0_s1, W1_s1, g1p, z1p, 16);
    k_zstats<<<128, 256>>>();

    k_pool<16><<<256, 256>>>(g1_s0, b1_s0, (const float*)z0p, e0p, 32, 256);
    k_pool<32><<<512, 256>>>(g1_s1, b1_s1, (const float*)z1p, e1p, 64, 272);

    k_fgemm<<<128, 256>>>(Wf);
    k_fbn<<<2048, 256>>>(gf, bf, (float*)d_out);
}

// round 5
// speedup vs baseline: 2.5820x; 1.1188x over previous
#include <cuda_runtime.h>
#include <math.h>

#define FULLMASK 0xffffffffu

#define BB 2
#define KK 2048
#define NN 16384
#define SROWS 65536      // B*K*16 sample-rows
#define ROWS 4096        // B*K
#define CBEV 256
#define HBEV 100
#define WBEV 176
#define FEAT_DIM 304
#define OUTC 128

// spatial hash for ball query
#define NXC 89
#define NYC 51
#define NCELL (NXC * NYC)    // 4539 per batch
#define CAP 64

// ---------------- scratch (device globals; no allocs allowed) ----------------
__device__ float4 g_g0[SROWS];            // grouped scale0: (rel xyz, feat)
__device__ float4 g_g1[SROWS];            // grouped scale1
__device__ unsigned char g_e0[ROWS];
__device__ unsigned char g_e1[ROWS];
__device__ float4 g_z0[SROWS * 4];        // scale0 layer1 pre-BN output (16 ch)
__device__ float4 g_z1[SROWS * 8];        // scale1 layer1 pre-BN output (32 ch)
__device__ float g_feats[ROWS * FEAT_DIM];
__device__ float g_fz[ROWS * OUTC];
__device__ float g_acc[512];              // stat accumulators
__device__ float4 g_cells[2 * NCELL * CAP];  // (x,y,z,idx-as-int)
__device__ int g_ccnt[2 * NCELL];

// acc layout:
//  [0:14)   s0 grouped moments: sum(4) then M upper-tri(10)
//  [16:30)  s1 grouped moments
//  [32:64)  s0 z stats (sum16 @32, sq16 @48)
//  [64:128) s1 z stats (sum32 @64, sq32 @96)
//  [160:288) final sum128 ; [288:416) final sq128

// ---------------- BEV bilinear gather -> feats[:, 0:256] --------------------
__global__ void k_bev(const float* __restrict__ kp, const float* __restrict__ sf,
                      const int* __restrict__ pstride) {
    int row = blockIdx.x;                  // 0..4095
    int b = row >> 11;
    float stride = (float)pstride[0];
    float kx = kp[row * 3 + 0];
    float ky = kp[row * 3 + 1];
    float x = (kx - (-70.4f)) / 0.1f / stride;
    float y = (ky - (-40.0f)) / 0.1f / stride;
    int xi = (int)floorf(x), yi = (int)floorf(y);
    int x0 = min(max(xi, 0), WBEV - 1), x1 = min(max(xi + 1, 0), WBEV - 1);
    int y0 = min(max(yi, 0), HBEV - 1), y1 = min(max(yi + 1, 0), HBEV - 1);
    float x0f = (float)x0, x1f = (float)x1, y0f = (float)y0, y1f = (float)y1;
    float wa = (x1f - x) * (y1f - y);
    float wb = (x1f - x) * (y - y0f);
    float wc = (x - x0f) * (y1f - y);
    float wd = (x - x0f) * (y - y0f);
    const float* base = sf + (size_t)b * CBEV * HBEV * WBEV;
    int c = threadIdx.x;                   // 256 threads = channels
    const float* pc = base + (size_t)c * (HBEV * WBEV);
    float Ia = __ldg(pc + y0 * WBEV + x0);
    float Ib = __ldg(pc + y1 * WBEV + x0);
    float Ic = __ldg(pc + y0 * WBEV + x1);
    float Id = __ldg(pc + y1 * WBEV + x1);
    g_feats[row * FEAT_DIM + c] = Ia * wa + Ib * wb + Ic * wc + Id * wd;
}

// ---------------- scatter points into 1.6m xy-cells --------------------------
__global__ void k_scatter(const float* __restrict__ pxyz) {
    int gid = blockIdx.x * 256 + threadIdx.x;     // 32768
    int b = gid >> 14;
    const float* p = pxyz + (size_t)gid * 3;
    float x = p[0], y = p[1], z = p[2];
    int cx = min(max((int)floorf((x + 70.4f) * 0.625f), 0), NXC - 1);
    int cy = min(max((int)floorf((y + 40.0f) * 0.625f), 0), NYC - 1);
    int cell = b * NCELL + cy * NXC + cx;
    int slot = atomicAdd(&g_ccnt[cell], 1);
    if (slot < CAP)
        g_cells[(size_t)cell * CAP + slot] =
            make_float4(x, y, z, __int_as_float(gid & 16383));
}

// ---------------- ball query via cells: warp per keypoint --------------------
__global__ void __launch_bounds__(256) k_group2(
        const float* __restrict__ kp, const float* __restrict__ pxyz,
        const float* __restrict__ pfeat) {
    __shared__ int s_hits[8][32];
    __shared__ int s_cnt[8];
    int wib = threadIdx.x >> 5, lane = threadIdx.x & 31;
    int kpid = blockIdx.x * 8 + wib;              // 512 CTAs x 8 warps = 4096
    int b = kpid >> 11;
    float kx = kp[kpid * 3 + 0], ky = kp[kpid * 3 + 1], kz = kp[kpid * 3 + 2];
    if (lane == 0) s_cnt[wib] = 0;
    __syncwarp();
    const float R0SQ = (float)(0.4 * 0.4);
    const float R1SQ = (float)(0.8 * 0.8);
    int cx0 = min(max((int)floorf((kx - 0.81f + 70.4f) * 0.625f), 0), NXC - 1);
    int cx1 = min(max((int)floorf((kx + 0.81f + 70.4f) * 0.625f), 0), NXC - 1);
    int cy0 = min(max((int)floorf((ky - 0.81f + 40.0f) * 0.625f), 0), NYC - 1);
    int cy1 = min(max((int)floorf((ky + 0.81f + 40.0f) * 0.625f), 0), NYC - 1);
    for (int cy = cy0; cy <= cy1; cy++) {
        for (int cx = cx0; cx <= cx1; cx++) {
            int cell = b * NCELL + cy * NXC + cx;
            int cnt = min(g_ccnt[cell], CAP);
            const float4* bp = &g_cells[(size_t)cell * CAP];
            for (int i = lane; i < cnt; i += 32) {
                float4 p = bp[i];
                float dx = kx - p.x, dy = ky - p.y, dz = kz - p.z;
                float d = __fadd_rn(__fadd_rn(__fmul_rn(dx, dx), __fmul_rn(dy, dy)),
                                    __fmul_rn(dz, dz));
                if (d < R1SQ) {
                    int pos = atomicAdd(&s_cnt[wib], 1);
                    if (pos < 32)
                        s_hits[wib][pos] = (__float_as_int(p.w) << 1) | (d < R0SQ ? 1 : 0);
                }
            }
        }
    }
    __syncwarp();
    int cnt = min(s_cnt[wib], 32);
    if (lane == 0 && cnt > 1) {            // insertion sort by (idx<<1|r0) = idx order
        for (int i = 1; i < cnt; i++) {
            int key = s_hits[wib][i];
            int j = i - 1;
            while (j >= 0 && s_hits[wib][j] > key) { s_hits[wib][j + 1] = s_hits[wib][j]; j--; }
            s_hits[wib][j + 1] = key;
        }
    }
    __syncwarp();
    int ent = (lane < cnt) ? s_hits[wib][lane] : 0;
    unsigned mask0 = __ballot_sync(FULLMASK, (lane < cnt) && (ent & 1));
    int n0 = __popc(mask0);
    int scale = (lane < 16) ? 1 : 0;
    int s = scale ? lane : (lane - 16);
    int myidx = -1;
    if (scale) {
        if (cnt > 0) myidx = ((s < cnt) ? s_hits[wib][s] : s_hits[wib][0]) >> 1;
    } else {
        if (n0 > 0) {
            int target = (s < n0) ? s : 0;
            unsigned m = mask0;
            for (int t = 0; t < target; t++) m &= m - 1;
            int pos = __ffs(m) - 1;
            myidx = s_hits[wib][pos] >> 1;
        }
    }
    float4 out = make_float4(0.f, 0.f, 0.f, 0.f);
    if (myidx >= 0) {
        const float* pp = pxyz + ((size_t)b * NN + myidx) * 3;
        out.x = pp[0] - kx;
        out.y = pp[1] - ky;
        out.z = pp[2] - kz;
        out.w = pfeat[(size_t)b * NN + myidx];
    }
    if (scale) g_g1[(size_t)kpid * 16 + s] = out;
    else       g_g0[(size_t)kpid * 16 + s] = out;
    if (s == 0) {
        if (scale) g_e1[kpid] = (cnt == 0);
        else       g_e0[kpid] = (n0 == 0);
    }
}

// ---------------- grouped-data moments (both scales) -------------------------
// warp shfl tree -> CTA shared reduction -> 28 global atomics per CTA
__global__ void k_moms() {
    __shared__ float s_red[28];
    int tid = threadIdx.x;
    int gid = blockIdx.x * 256 + tid;        // 64 blocks x 256 = 16384 threads
    if (tid < 28) s_red[tid] = 0.f;
    __syncthreads();
    float a[28];
#pragma unroll
    for (int v = 0; v < 28; v++) a[v] = 0.f;
#pragma unroll
    for (int sc = 0; sc < 2; sc++) {
        const float4* G = sc ? g_g1 : g_g0;
        float* p = a + sc * 14;
        for (int r = gid; r < SROWS; r += 16384) {
            float4 g = G[r];
            p[0] += g.x; p[1] += g.y; p[2] += g.z; p[3] += g.w;
            p[4] += g.x * g.x; p[5] += g.x * g.y; p[6] += g.x * g.z; p[7] += g.x * g.w;
            p[8] += g.y * g.y; p[9] += g.y * g.z; p[10] += g.y * g.w;
            p[11] += g.z * g.z; p[12] += g.z * g.w; p[13] += g.w * g.w;
        }
    }
    int lane = tid & 31;
#pragma unroll
    for (int v = 0; v < 28; v++) {
        float val = a[v];
        val += __shfl_down_sync(FULLMASK, val, 16);
        val += __shfl_down_sync(FULLMASK, val, 8);
        val += __shfl_down_sync(FULLMASK, val, 4);
        val += __shfl_down_sync(FULLMASK, val, 2);
        val += __shfl_down_sync(FULLMASK, val, 1);
        if (lane == 0) atomicAdd(&s_red[v], val);
    }
    __syncthreads();
    if (tid < 28) atomicAdd(&g_acc[(tid < 14) ? tid : (tid - 14 + 16)], s_red[tid]);
}

// ---------------- fused MLP: pure stream, bn0 analytic ----------------------
template <int C>
__global__ void __launch_bounds__(256) k_mlp(
        const float* __restrict__ W0, const float* __restrict__ gamma0,
        const float* __restrict__ beta0, const float* __restrict__ W1,
        const float4* __restrict__ Gin, float4* __restrict__ Zout, int momOff) {
    __shared__ float sW0[64];
    __shared__ float sW1[C * 16];
    __shared__ float sA[16], sB[16];
    int tid = threadIdx.x;
    if (tid < 64) sW0[tid] = W0[tid];
    for (int i = tid; i < C * 16; i += 256) sW1[i] = W1[i];
    __syncthreads();
    if (tid < 16) {
        float w0 = sW0[tid * 4 + 0], w1 = sW0[tid * 4 + 1];
        float w2 = sW0[tid * 4 + 2], w3 = sW0[tid * 4 + 3];
        const float* m = &g_acc[momOff];
        float mean = (w0 * m[0] + w1 * m[1] + w2 * m[2] + w3 * m[3]) * (1.0f / 65536.0f);
        float e2 = w0 * w0 * m[4] + w1 * w1 * m[8] + w2 * w2 * m[11] + w3 * w3 * m[13]
                 + 2.f * (w0 * w1 * m[5] + w0 * w2 * m[6] + w0 * w3 * m[7]
                        + w1 * w2 * m[9] + w1 * w3 * m[10] + w2 * w3 * m[12]);
        e2 *= (1.0f / 65536.0f);
        float var = e2 - mean * mean;
        float sc = gamma0[tid] * rsqrtf(var + 1e-5f);
        sA[tid] = sc;
        sB[tid] = beta0[tid] - mean * sc;
    }
    __syncthreads();
    int row = blockIdx.x * 256 + tid;        // 256 blocks
    float4 g = Gin[row];
    float y[16];
#pragma unroll
    for (int o = 0; o < 16; o++) {
        float z = g.x * sW0[o * 4 + 0] + g.y * sW0[o * 4 + 1] +
                  g.z * sW0[o * 4 + 2] + g.w * sW0[o * 4 + 3];
        y[o] = fmaxf(z * sA[o] + sB[o], 0.f);
    }
#pragma unroll
    for (int o4 = 0; o4 < C / 4; o4++) {
        float zq[4];
#pragma unroll
        for (int oo = 0; oo < 4; oo++) {
            int o = o4 * 4 + oo;
            float z = 0.f;
#pragma unroll
            for (int c = 0; c < 16; c++) z += y[c] * sW1[o * 16 + c];
            zq[oo] = z;
        }
        Zout[(size_t)row * (C / 4) + o4] = make_float4(zq[0], zq[1], zq[2], zq[3]);
    }
}

// ---------------- z stats: lane == channel, zero shuffles --------------------
__global__ void __launch_bounds__(256) k_zstats() {
    __shared__ float r1[64], r0[32];
    int tid = threadIdx.x;
    int gt = blockIdx.x * 256 + tid;          // 128 CTAs -> 32768 threads
    if (tid < 64) r1[tid] = 0.f;
    if (tid < 32) r0[tid] = 0.f;
    __syncthreads();
    const float* Z1 = (const float*)g_z1;     // 2M floats, channel = f & 31
    float s = 0.f, q = 0.f;
    for (int f = gt; f < SROWS * 32; f += 32768) {
        float v = Z1[f];
        s += v; q += v * v;
    }
    atomicAdd(&r1[tid & 31], s);
    atomicAdd(&r1[32 + (tid & 31)], q);
    const float* Z0 = (const float*)g_z0;     // 1M floats, channel = f & 15
    s = 0.f; q = 0.f;
    for (int f = gt; f < SROWS * 16; f += 32768) {
        float v = Z0[f];
        s += v; q += v * v;
    }
    atomicAdd(&r0[tid & 15], s);
    atomicAdd(&r0[16 + (tid & 15)], q);
    __syncthreads();
    if (tid < 64) atomicAdd(&g_acc[64 + tid], r1[tid]);   // s1: sum32@64, sq32@96
    else if (tid < 96) atomicAdd(&g_acc[32 + tid - 64], r0[tid - 64]); // s0 @32/@48
}

// ---------------- bn+relu+maxpool over 16 samples -> feats ------------------
template <int C>
__global__ void k_pool(const float* __restrict__ gamma, const float* __restrict__ beta,
                       const float* __restrict__ Z, const unsigned char* __restrict__ E,
                       int accOff, int colbase) {
    int gid = blockIdx.x * 256 + threadIdx.x;     // ROWS*C threads
    int k = gid / C, o = gid - k * C;
    float mean = g_acc[accOff + o] * (1.0f / 65536.0f);
    float var = g_acc[accOff + C + o] * (1.0f / 65536.0f) - mean * mean;
    float a = gamma[o] * rsqrtf(var + 1e-5f);
    float bb = beta[o] - mean * a;
    const float* zp = Z + ((size_t)k * 16) * C + o;
    float mx = 0.f;
#pragma unroll
    for (int s = 0; s < 16; s++) {
        float v = fmaxf(zp[s * C] * a + bb, 0.f);
        mx = fmaxf(mx, v);
    }
    if (E[k]) mx = 0.f;
    g_feats[(size_t)k * FEAT_DIM + colbase + o] = mx;
}

// ---------------- final GEMM: feats(4096,304) @ Wf(128,304)^T + stats -------
__global__ void __launch_bounds__(256) k_fgemm(const float* __restrict__ Wf) {
    __shared__ float sF[32 * FEAT_DIM];          // 38.9 KB
    __shared__ float sS[128], sQ[128];
    int tid = threadIdx.x;
    int r0 = blockIdx.x * 32;                    // 128 CTAs
    const float4* src = (const float4*)(g_feats + (size_t)r0 * FEAT_DIM);
    float4* dst = (float4*)sF;
    for (int i = tid; i < 32 * (FEAT_DIM / 4); i += 256) dst[i] = src[i];
    if (tid < 128) { sS[tid] = 0.f; sQ[tid] = 0.f; }
    __syncthreads();
    int o = tid & 127;
    int rh = tid >> 7;
    float acc_[16];
#pragma unroll
    for (int r = 0; r < 16; r++) acc_[r] = 0.f;
    const float4* wrow = (const float4*)(Wf + (size_t)o * FEAT_DIM);
    const float4* fbase = (const float4*)sF + (size_t)(rh * 16) * (FEAT_DIM / 4);
#pragma unroll 2
    for (int c4 = 0; c4 < FEAT_DIM / 4; c4++) {
        float4 w = __ldg(wrow + c4);
#pragma unroll
        for (int r = 0; r < 16; r++) {
            float4 f = fbase[(size_t)r * (FEAT_DIM / 4) + c4];
            acc_[r] += w.x * f.x + w.y * f.y + w.z * f.z + w.w * f.w;
        }
    }
    float S = 0.f, Q = 0.f;
#pragma unroll
    for (int r = 0; r < 16; r++) {
        float z = acc_[r];
        g_fz[(size_t)(r0 + rh * 16 + r) * OUTC + o] = z;
        S += z; Q += z * z;
    }
    atomicAdd(&sS[o], S);
    atomicAdd(&sQ[o], Q);
    __syncthreads();
    if (tid < 128) {
        atomicAdd(&g_acc[160 + tid], sS[tid]);
        atomicAdd(&g_acc[288 + tid], sQ[tid]);
    }
}

// ---------------- final bn + relu -> d_out ----------------------------------
__global__ void k_fbn(const float* __restrict__ gamma, const float* __restrict__ beta,
                      float* __restrict__ out) {
    int gid = blockIdx.x * 256 + threadIdx.x;     // 524288
    int o = gid & 127;
    float mean = g_acc[160 + o] * (1.0f / 4096.0f);
    float var = g_acc[288 + o] * (1.0f / 4096.0f) - mean * mean;
    float v = (g_fz[gid] - mean) * rsqrtf(var + 1e-5f) * gamma[o] + beta[o];
    out[gid] = fmaxf(v, 0.f);
}

// ---------------- launch -----------------------------------------------------
extern "C" void kernel_launch(void* const* d_in, const int* in_sizes, int n_in,
                              void* d_out, int out_size) {
    const float* kp     = (const float*)d_in[0];
    const float* pxyz   = (const float*)d_in[1];
    const float* pfeat  = (const float*)d_in[2];
    const float* sf     = (const float*)d_in[3];
    const int*   stridep= (const int*)d_in[4];
    const float* W0_s0  = (const float*)d_in[5];
    const float* g0_s0  = (const float*)d_in[6];
    const float* b0_s0  = (const float*)d_in[7];
    const float* W1_s0  = (const float*)d_in[8];
    const float* g1_s0  = (const float*)d_in[9];
    const float* b1_s0  = (const float*)d_in[10];
    const float* W0_s1  = (const float*)d_in[11];
    const float* g0_s1  = (const float*)d_in[12];
    const float* b0_s1  = (const float*)d_in[13];
    const float* W1_s1  = (const float*)d_in[14];
    const float* g1_s1  = (const float*)d_in[15];
    const float* b1_s1  = (const float*)d_in[16];
    const float* Wf     = (const float*)d_in[17];
    const float* gf     = (const float*)d_in[18];
    const float* bf     = (const float*)d_in[19];
    (void)in_sizes; (void)n_in; (void)out_size;

    float4* z0p; cudaGetSymbolAddress((void**)&z0p, g_z0);
    float4* z1p; cudaGetSymbolAddress((void**)&z1p, g_z1);
    float4* g0p; cudaGetSymbolAddress((void**)&g0p, g_g0);
    float4* g1p; cudaGetSymbolAddress((void**)&g1p, g_g1);
    unsigned char* e0p; cudaGetSymbolAddress((void**)&e0p, g_e0);
    unsigned char* e1p; cudaGetSymbolAddress((void**)&e1p, g_e1);
    void* accp; cudaGetSymbolAddress(&accp, g_acc);
    void* ccntp; cudaGetSymbolAddress(&ccntp, g_ccnt);

    cudaMemsetAsync(accp, 0, 512 * sizeof(float));
    cudaMemsetAsync(ccntp, 0, 2 * NCELL * sizeof(int));

    k_bev<<<4096, 256>>>(kp, sf, stridep);
    k_scatter<<<128, 256>>>(pxyz);
    k_group2<<<512, 256>>>(kp, pxyz, pfeat);
    k_moms<<<64, 256>>>();

    k_mlp<16><<<256, 256>>>(W0_s0, g0_s0, b0_s0, W1_s0, g0p, z0p, 0);
    k_mlp<32><<<256, 256>>>(W0_s1, g0_s1, b0_s1, W1_s1, g1p, z1p, 16);
    k_zstats<<<128, 256>>>();

    k_pool<16><<<256, 256>>>(g1_s0, b1_s0, (const float*)z0p, e0p, 32, 256);
    k_pool<32><<<512, 256>>>(g1_s1, b1_s1, (const float*)z1p, e1p, 64, 272);

    k_fgemm<<<128, 256>>>(Wf);
    k_fbn<<<2048, 256>>>(gf, bf, (float*)d_out);
}